// round 15
// baseline (speedup 1.0000x reference)
#include <cuda_runtime.h>
#include <cuda_fp16.h>
#include <cstdint>
#include <cstddef>

#define NPIX 16384
#define CHN 128
#define BATCH 4
#define NSLICE 64

// ---------------- scratch (device globals; no allocation allowed) -------------
__device__ __align__(16) __half g_cath[BATCH * 8 * NPIX * 16];   // cat, fp16 interleaved
__device__ __align__(16) __half g_buf1h[BATCH * 8 * NPIX * 16];  // conv1 out, interleaved
__device__ __align__(16) __half g_feath[BATCH * CHN * NPIX];     // feat fp16 [c][n]
__device__ __align__(16) __half g_feati[BATCH * 8 * NPIX * 16];  // feat fp16 interleaved
__device__ __align__(16) __half g_x1h[BATCH * 64 * NPIX];        // x1 fp16 [c][n]
__device__ float g_gpart[NSLICE * BATCH * CHN * CHN];
__device__ float g_G[BATCH * CHN * CHN];
__device__ float g_tpart[NSLICE * BATCH * CHN * 64];
__device__ float g_t[BATCH * CHN * 64];               // reduced t
__device__ float g_t2[BATCH * CHN * 64];              // G^{-1} t
// fp16 conv weight fragments: [chunk8][tap9][mfrag8][lane32] uint4
__device__ uint32_t g_wh1[8 * 9 * 8 * 32 * 4];
__device__ uint32_t g_wh2[8 * 9 * 8 * 32 * 4];
__device__ uint32_t g_wih[8 * 8 * 32 * 4];            // 1x1 fp16 fragments

__device__ __forceinline__ float leakyf(float v) { return v >= 0.f ? v : 0.2f * v; }

__device__ __forceinline__ void mma_f16(float* acc, const uint4& a, uint32_t b0, uint32_t b1) {
    asm volatile(
        "mma.sync.aligned.m16n8k16.row.col.f32.f16.f16.f32 "
        "{%0,%1,%2,%3}, {%4,%5,%6,%7}, {%8,%9}, {%0,%1,%2,%3};"
        : "+f"(acc[0]), "+f"(acc[1]), "+f"(acc[2]), "+f"(acc[3])
        : "r"(a.x), "r"(a.y), "r"(a.z), "r"(a.w), "r"(b0), "r"(b1));
}

__device__ __forceinline__ uint32_t smem_u32(const void* p) {
    return (uint32_t)__cvta_generic_to_shared(p);
}
__device__ __forceinline__ void cp16(uint32_t s, const void* g) {
    asm volatile("cp.async.cg.shared.global [%0], [%1], 16;" :: "r"(s), "l"(g));
}
__device__ __forceinline__ void cp16z(uint32_t s, const void* g, int valid16) {
    asm volatile("cp.async.cg.shared.global [%0], [%1], 16, %2;"
                 :: "r"(s), "l"(g), "r"(valid16));
}
#define CP_COMMIT() asm volatile("cp.async.commit_group;")
#define CP_WAIT1() asm volatile("cp.async.wait_group 1;")
#define CP_WAIT0() asm volatile("cp.async.wait_group 0;")

__device__ __forceinline__ uint32_t pack_h2(float lo, float hi) {
    __half2 h = __floats2half2_rn(lo, hi);
    return *(uint32_t*)&h;
}
// permuted ic position inside 16-ic group (matches m16n8k16 B-fragment order)
__device__ __forceinline__ int icpos(int k) {
    return (k < 8) ? ((k >> 1) * 4 + (k & 1)) : (((k - 8) >> 1) * 4 + 2 + (k & 1));
}

// ---------------- prep (smem transpose, coalesced) + weight repack ------------
__device__ __forceinline__ void repack_wh(const float* __restrict__ w, uint4* __restrict__ out,
                                          int idx)
{
    int lane = idx & 31;
    int t = idx >> 5;
    int mf = t & 7;
    int t2 = t >> 3;
    int tap = t2 % 9;
    int chunk = t2 / 9;
    int lq = lane >> 2, lr = lane & 3;
    int oc0 = mf * 16 + lq, oc1 = oc0 + 8;
    int kb = chunk * 16;
    uint4 o;
    o.x = pack_h2(w[((size_t)oc0 * CHN + kb + 2 * lr) * 9 + tap],
                  w[((size_t)oc0 * CHN + kb + 2 * lr + 1) * 9 + tap]);
    o.y = pack_h2(w[((size_t)oc1 * CHN + kb + 2 * lr) * 9 + tap],
                  w[((size_t)oc1 * CHN + kb + 2 * lr + 1) * 9 + tap]);
    o.z = pack_h2(w[((size_t)oc0 * CHN + kb + 8 + 2 * lr) * 9 + tap],
                  w[((size_t)oc0 * CHN + kb + 9 + 2 * lr) * 9 + tap]);
    o.w = pack_h2(w[((size_t)oc1 * CHN + kb + 8 + 2 * lr) * 9 + tap],
                  w[((size_t)oc1 * CHN + kb + 9 + 2 * lr) * 9 + tap]);
    out[idx] = o;
}

__global__ void prep_repack_kernel(const float* __restrict__ x1, const float* __restrict__ x2,
                                   const float* __restrict__ w1, const float* __restrict__ w2,
                                   const float* __restrict__ wi,
                                   uint32_t* __restrict__ wh1, uint32_t* __restrict__ wh2,
                                   uint32_t* __restrict__ wih)
{
    __shared__ __half sT[16][264];
    int bx = blockIdx.x;
    int tid = threadIdx.x;
    if (bx < 2048) {
        int b = bx >> 9;
        int rem = bx & 511;
        int chunk = rem >> 6;
        int n0 = (rem & 63) * 256;
#pragma unroll
        for (int k = 0; k < 16; k++) {
            int ic = chunk * 16 + k;
            const float* src = (ic < 64) ? x1 + ((size_t)(b * 64 + ic) << 14)
                                         : x2 + ((size_t)(b * 64 + ic - 64) << 14);
            sT[k][tid] = __float2half_rn(src[n0 + tid]);
        }
        __syncthreads();
        __half v[16];
#pragma unroll
        for (int k = 0; k < 16; k++) v[icpos(k)] = sT[k][tid];
        __half* dst = g_cath + (((size_t)(b * 8 + chunk) * NPIX + n0 + tid) << 4);
        *(uint4*)dst = *(uint4*)&v[0];
        *(uint4*)(dst + 8) = *(uint4*)&v[8];
        if (chunk < 4) {  // fp16 copy of x1 for gemmT (coalesced)
#pragma unroll
            for (int k = 0; k < 16; k++)
                g_x1h[((size_t)(b * 64 + chunk * 16 + k)) * NPIX + n0 + tid] = sT[k][tid];
        }
    } else if (bx < 2120) {
        int idx = (bx - 2048) * 256 + tid;
        if (idx < 18432) repack_wh(w1, (uint4*)wh1, idx);
    } else if (bx < 2192) {
        int idx = (bx - 2120) * 256 + tid;
        if (idx < 18432) repack_wh(w2, (uint4*)wh2, idx);
    } else {
        int idx = (bx - 2192) * 256 + tid;
        if (idx >= 2048) return;
        int lane = idx & 31;
        int t = idx >> 5;
        int mf = t & 7;
        int chunk = t >> 3;
        int lq = lane >> 2, lr = lane & 3;
        int oc0 = mf * 16 + lq, oc1 = oc0 + 8;
        int kb = chunk * 16;
        uint4 o;
        o.x = pack_h2(wi[(size_t)oc0 * CHN + kb + 2 * lr], wi[(size_t)oc0 * CHN + kb + 2 * lr + 1]);
        o.y = pack_h2(wi[(size_t)oc1 * CHN + kb + 2 * lr], wi[(size_t)oc1 * CHN + kb + 2 * lr + 1]);
        o.z = pack_h2(wi[(size_t)oc0 * CHN + kb + 8 + 2 * lr], wi[(size_t)oc0 * CHN + kb + 9 + 2 * lr]);
        o.w = pack_h2(wi[(size_t)oc1 * CHN + kb + 8 + 2 * lr], wi[(size_t)oc1 * CHN + kb + 9 + 2 * lr]);
        ((uint4*)wih)[idx] = o;
    }
}

// ---------------- conv 3x3 via fp16 m16n8k16, weights via direct LDG ---------
template <bool FIRST>
__global__ __launch_bounds__(256, 2) void conv_fp16_kernel(const float* __restrict__ bias)
{
    __shared__ __half sIn[2][2880];            // [10 rows][18 px][16 icperm]

    const int tid = threadIdx.x;
    const int lane = tid & 31;
    const int wid = tid >> 5;
    const int warpM = wid & 3;
    const int warpN = wid >> 2;
    const int lq = lane >> 2;
    const int lr = lane & 3;
    const int b = blockIdx.z;
    const int r0 = blockIdx.y * 8;
    const int c0 = blockIdx.x * 16;

    float acc[2][8][4];
#pragma unroll
    for (int m = 0; m < 2; m++)
#pragma unroll
        for (int j = 0; j < 8; j++)
#pragma unroll
            for (int e = 0; e < 4; e++) acc[m][j][e] = 0.f;

    const uint4* wsrc = (const uint4*)(FIRST ? g_wh1 : g_wh2);
    const uint4* wwarp0 = wsrc + (warpM * 2 + 0) * 32 + lane;
    const uint4* wwarp1 = wsrc + (warpM * 2 + 1) * 32 + lane;
    const __half* ibase = (FIRST ? g_cath : g_buf1h) + ((size_t)b * 8 * NPIX << 4);

    // hoisted staging descriptors
    uint32_t sOff0 = 0, sOff1 = 0;
    size_t gOff0 = 0, gOff1 = 0;
    int vld0 = 0, vld1 = 0;
    {
        int i = tid;
        int row = i / 36;
        int p2 = i - row * 36;
        int px = p2 >> 1, hp = p2 & 1;
        int gr = r0 - 1 + row, gc = c0 - 1 + px;
        vld0 = (((unsigned)gr < 128u) && ((unsigned)gc < 128u)) ? 16 : 0;
        gOff0 = (((size_t)(vld0 ? gr * 128 + gc : 0)) << 4) + hp * 8;
        sOff0 = (uint32_t)(row * 288 + px * 16 + hp * 8);
        i = tid + 256;
        if (i < 360) {
            row = i / 36;
            p2 = i - row * 36;
            px = p2 >> 1; hp = p2 & 1;
            gr = r0 - 1 + row; gc = c0 - 1 + px;
            vld1 = (((unsigned)gr < 128u) && ((unsigned)gc < 128u)) ? 16 : 0;
            gOff1 = (((size_t)(vld1 ? gr * 128 + gc : 0)) << 4) + hp * 8;
            sOff1 = (uint32_t)(row * 288 + px * 16 + hp * 8);
        }
    }
    const bool has1 = (tid + 256) < 360;

    auto stin = [&](int buf, int cc) {
        const __half* src = ibase + ((size_t)cc * NPIX << 4);
        uint32_t sb = smem_u32(sIn[buf]);
        cp16z(sb + sOff0 * 2, src + gOff0, vld0);
        if (has1) cp16z(sb + sOff1 * 2, src + gOff1, vld1);
    };

    stin(0, 0);
    CP_COMMIT();

    uint4 a0 = __ldg(wwarp0);
    uint4 a1 = __ldg(wwarp1);

    for (int cc = 0; cc < 8; cc++) {
        if (cc < 7) {
            stin((cc + 1) & 1, cc + 1);
            CP_COMMIT();
            CP_WAIT1();
        } else {
            CP_WAIT0();
        }
        __syncthreads();

        const __half* ib = sIn[cc & 1];
#pragma unroll
        for (int tap = 0; tap < 9; tap++) {
            const int dr = tap / 3, dc = tap % 3;
            uint2 bv[8];
#pragma unroll
            for (int j = 0; j < 8; j++) {
                int row = warpN * 4 + (j >> 1) + dr;
                int slot = (j & 1) * 8 + lq + dc;
                bv[j] = *(const uint2*)(ib + row * 288 + slot * 16 + lr * 4);
            }
            int s = cc * 9 + tap;
            uint4 na0, na1;
            if (s < 71) {
                na0 = __ldg(wwarp0 + (s + 1) * 256);
                na1 = __ldg(wwarp1 + (s + 1) * 256);
            }
#pragma unroll
            for (int j = 0; j < 8; j++) {
                mma_f16(acc[0][j], a0, bv[j].x, bv[j].y);
                mma_f16(acc[1][j], a1, bv[j].x, bv[j].y);
            }
            if (s < 71) { a0 = na0; a1 = na1; }
        }
        __syncthreads();
    }

    // ---- epilogue ----
#pragma unroll
    for (int m = 0; m < 2; m++) {
        int oc = warpM * 32 + m * 16 + lq;
        float bv0 = bias[oc], bv1 = bias[oc + 8];
        const int chunk = warpM * 2 + m;
        const int ip0 = icpos(lq), ip1 = icpos(lq + 8);
        if (FIRST) {
            __half* hb = g_buf1h + (((size_t)(b * 8 + chunk) * NPIX) << 4);
#pragma unroll
            for (int j = 0; j < 8; j++) {
                int pix = (r0 + warpN * 4 + (j >> 1)) * 128 + c0 + (j & 1) * 8 + lr * 2;
                __half* p = hb + ((size_t)pix << 4);
                p[ip0] = __float2half_rn(leakyf(acc[m][j][0] + bv0));
                p[16 + ip0] = __float2half_rn(leakyf(acc[m][j][1] + bv0));
                p[ip1] = __float2half_rn(leakyf(acc[m][j][2] + bv1));
                p[16 + ip1] = __float2half_rn(leakyf(acc[m][j][3] + bv1));
            }
        } else {
            __half* hi = g_feati + (((size_t)(b * 8 + chunk) * NPIX) << 4);
            __half* hf0 = g_feath + ((size_t)(b * CHN + oc)) * NPIX;
            __half* hf1 = hf0 + (size_t)8 * NPIX;
#pragma unroll
            for (int j = 0; j < 8; j++) {
                int pix = (r0 + warpN * 4 + (j >> 1)) * 128 + c0 + (j & 1) * 8 + lr * 2;
                __half2 q0 = *(__half2*)(hf0 + pix);
                __half2 q1 = *(__half2*)(hf1 + pix);
                float v00 = __low2float(q0) + leakyf(acc[m][j][0] + bv0);
                float v01 = __high2float(q0) + leakyf(acc[m][j][1] + bv0);
                float v10 = __low2float(q1) + leakyf(acc[m][j][2] + bv1);
                float v11 = __high2float(q1) + leakyf(acc[m][j][3] + bv1);
                *(__half2*)(hf0 + pix) = __floats2half2_rn(v00, v01);
                *(__half2*)(hf1 + pix) = __floats2half2_rn(v10, v11);
                __half* p = hi + ((size_t)pix << 4);
                p[ip0] = __float2half_rn(v00);
                p[16 + ip0] = __float2half_rn(v01);
                p[ip1] = __float2half_rn(v10);
                p[16 + ip1] = __float2half_rn(v11);
            }
        }
    }
}

// ---------------- 1x1 conv via fp16 m16n8k16 (reuses g_cath) ------------------
__global__ __launch_bounds__(256) void gemm1x1h_kernel(const float* __restrict__ bi)
{
    __shared__ uint4 sW1[2][256];
    __shared__ __half sB[2][2048];

    const int tid = threadIdx.x;
    const int lane = tid & 31;
    const int wid = tid >> 5;
    const int warpM = wid & 3;
    const int warpN = wid >> 2;
    const int lq = lane >> 2;
    const int lr = lane & 3;
    const int b = blockIdx.z;
    const int r0 = blockIdx.y * 8;
    const int c0 = blockIdx.x * 16;

    float acc[2][8][4];
#pragma unroll
    for (int m = 0; m < 2; m++)
#pragma unroll
        for (int j = 0; j < 8; j++)
#pragma unroll
            for (int e = 0; e < 4; e++) acc[m][j][e] = 0.f;

    const __half* ibase = g_cath + ((size_t)b * 8 * NPIX << 4);

    auto stage = [&](int buf, int cc) {
        int hp = tid & 1;
        int pl = tid >> 1;
        int row = pl >> 4, px = pl & 15;
        int pix = (r0 + row) * 128 + c0 + px;
        cp16(smem_u32(&sB[buf][(row * 16 + px) * 16 + hp * 8]),
             ibase + ((size_t)cc * NPIX << 4) + ((size_t)pix << 4) + hp * 8);
        cp16(smem_u32(&sW1[buf][tid]), ((const uint4*)g_wih) + cc * 256 + tid);
    };

    stage(0, 0);
    CP_COMMIT();

    for (int cc = 0; cc < 8; cc++) {
        if (cc < 7) {
            stage((cc + 1) & 1, cc + 1);
            CP_COMMIT();
            CP_WAIT1();
        } else {
            CP_WAIT0();
        }
        __syncthreads();

        uint4 a0 = sW1[cc & 1][(warpM * 2 + 0) * 32 + lane];
        uint4 a1 = sW1[cc & 1][(warpM * 2 + 1) * 32 + lane];
        const __half* ib = sB[cc & 1];
        uint2 bv[8];
#pragma unroll
        for (int j = 0; j < 8; j++) {
            int row = warpN * 4 + (j >> 1);
            int slot = (j & 1) * 8 + lq;
            bv[j] = *(const uint2*)(ib + (row * 16 + slot) * 16 + lr * 4);
        }
#pragma unroll
        for (int j = 0; j < 8; j++) {
            mma_f16(acc[0][j], a0, bv[j].x, bv[j].y);
            mma_f16(acc[1][j], a1, bv[j].x, bv[j].y);
        }
        __syncthreads();
    }

#pragma unroll
    for (int m = 0; m < 2; m++) {
        int oc = warpM * 32 + m * 16 + lq;
        float b0 = bi[oc], b1 = bi[oc + 8];
        __half* hf0 = g_feath + ((size_t)(b * CHN + oc)) * NPIX;
        __half* hf1 = hf0 + (size_t)8 * NPIX;
#pragma unroll
        for (int j = 0; j < 8; j++) {
            int pix = (r0 + warpN * 4 + (j >> 1)) * 128 + c0 + (j & 1) * 8 + lr * 2;
            *(__half2*)(hf0 + pix) = __floats2half2_rn(acc[m][j][0] + b0, acc[m][j][1] + b0);
            *(__half2*)(hf1 + pix) = __floats2half2_rn(acc[m][j][2] + b1, acc[m][j][3] + b1);
        }
    }
}

// ---------------- G = V V^T via fp16 mma, split-K -----------------------------
// (Projection invariant to V row scaling; reference L1 normalization skipped.)
__global__ __launch_bounds__(256, 2) void gemmGh_kernel()
{
    __shared__ __half sV[2][128 * 24];   // stride 24 halves = 12 words, conflict-free
    const int tid = threadIdx.x;
    const int lane = tid & 31;
    const int wid = tid >> 5;
    const int warpM = wid & 3;
    const int warpN = wid >> 2;
    const int lq = lane >> 2;
    const int lr = lane & 3;
    const int slice = blockIdx.x, b = blockIdx.y;
    const __half* base = g_feath + (size_t)b * CHN * NPIX;
    const int k0g = slice * 256;

    float acc[2][8][4];
#pragma unroll
    for (int mi = 0; mi < 2; mi++)
#pragma unroll
        for (int nj = 0; nj < 8; nj++)
#pragma unroll
            for (int e = 0; e < 4; e++) acc[mi][nj][e] = 0.f;

    auto stage = [&](int buf, int kc) {
        int kk = k0g + kc * 16;
        int c = tid >> 1, part = tid & 1;
        cp16(smem_u32(&sV[buf][c * 24 + part * 8]), base + (size_t)c * NPIX + kk + part * 8);
    };
    stage(0, 0);
    CP_COMMIT();

    for (int kc = 0; kc < 16; kc++) {
        if (kc < 15) {
            stage((kc + 1) & 1, kc + 1);
            CP_COMMIT();
            CP_WAIT1();
        } else {
            CP_WAIT0();
        }
        __syncthreads();
        const uint32_t* sv = (const uint32_t*)sV[kc & 1];   // row stride 12 words
        uint4 af[2];
#pragma unroll
        for (int mi = 0; mi < 2; mi++) {
            int m0 = warpM * 32 + mi * 16;
            af[mi].x = sv[(m0 + lq) * 12 + lr];
            af[mi].y = sv[(m0 + lq + 8) * 12 + lr];
            af[mi].z = sv[(m0 + lq) * 12 + 4 + lr];
            af[mi].w = sv[(m0 + lq + 8) * 12 + 4 + lr];
        }
#pragma unroll
        for (int nj = 0; nj < 8; nj++) {
            int n0 = warpN * 64 + nj * 8;
            uint32_t b0 = sv[(n0 + lq) * 12 + lr];
            uint32_t b1 = sv[(n0 + lq) * 12 + 4 + lr];
            mma_f16(acc[0][nj], af[0], b0, b1);
            mma_f16(acc[1][nj], af[1], b0, b1);
        }
        __syncthreads();
    }

    float* outp = g_gpart + ((size_t)slice * BATCH + b) * CHN * CHN;
#pragma unroll
    for (int mi = 0; mi < 2; mi++) {
        int m0 = warpM * 32 + mi * 16 + lq;
#pragma unroll
        for (int nj = 0; nj < 8; nj++) {
            int n = warpN * 64 + nj * 8 + lr * 2;
            *(float2*)(outp + m0 * 128 + n) = make_float2(acc[mi][nj][0], acc[mi][nj][1]);
            *(float2*)(outp + (m0 + 8) * 128 + n) = make_float2(acc[mi][nj][2], acc[mi][nj][3]);
        }
    }
}

// ---------------- t = V @ x1^T via fp16 mma, split-K --------------------------
__global__ __launch_bounds__(256, 2) void gemmTh_kernel()
{
    __shared__ __half sV[2][128 * 24];
    __shared__ __half sX[2][64 * 24];
    const int tid = threadIdx.x;
    const int lane = tid & 31;
    const int wid = tid >> 5;
    const int warpM = wid & 3;
    const int warpN = wid >> 2;
    const int lq = lane >> 2;
    const int lr = lane & 3;
    const int slice = blockIdx.x, b = blockIdx.y;
    const __half* vbase = g_feath + (size_t)b * CHN * NPIX;
    const __half* xbase = g_x1h + (size_t)b * 64 * NPIX;
    const int k0g = slice * 256;

    float acc[2][4][4];
#pragma unroll
    for (int mi = 0; mi < 2; mi++)
#pragma unroll
        for (int nj = 0; nj < 4; nj++)
#pragma unroll
            for (int e = 0; e < 4; e++) acc[mi][nj][e] = 0.f;

    auto stage = [&](int buf, int kc) {
        int kk = k0g + kc * 16;
        int c = tid >> 1, part = tid & 1;
        cp16(smem_u32(&sV[buf][c * 24 + part * 8]), vbase + (size_t)c * NPIX + kk + part * 8);
        if (tid < 128)
            cp16(smem_u32(&sX[buf][c * 24 + part * 8]), xbase + (size_t)c * NPIX + kk + part * 8);
    };
    stage(0, 0);
    CP_COMMIT();

    for (int kc = 0; kc < 16; kc++) {
        if (kc < 15) {
            stage((kc + 1) & 1, kc + 1);
            CP_COMMIT();
            CP_WAIT1();
        } else {
            CP_WAIT0();
        }
        __syncthreads();
        const uint32_t* sv = (const uint32_t*)sV[kc & 1];
        const uint32_t* sx = (const uint32_t*)sX[kc & 1];
        uint4 af[2];
#pragma unroll
        for (int mi = 0; mi < 2; mi++) {
            int m0 = warpM * 32 + mi * 16;
            af[mi].x = sv[(m0 + lq) * 12 + lr];
            af[mi].y = sv[(m0 + lq + 8) * 12 + lr];
            af[mi].z = sv[(m0 + lq) * 12 + 4 + lr];
            af[mi].w = sv[(m0 + lq + 8) * 12 + 4 + lr];
        }
#pragma unroll
        for (int nj = 0; nj < 4; nj++) {
            int n0 = warpN * 32 + nj * 8;
            uint32_t b0 = sx[(n0 + lq) * 12 + lr];
            uint32_t b1 = sx[(n0 + lq) * 12 + 4 + lr];
            mma_f16(acc[0][nj], af[0], b0, b1);
            mma_f16(acc[1][nj], af[1], b0, b1);
        }
        __syncthreads();
    }

    float* outp = g_tpart + ((size_t)slice * BATCH + b) * CHN * 64;
#pragma unroll
    for (int mi = 0; mi < 2; mi++) {
        int m0 = warpM * 32 + mi * 16 + lq;
#pragma unroll
        for (int nj = 0; nj < 4; nj++) {
            int n = warpN * 32 + nj * 8 + lr * 2;
            *(float2*)(outp + m0 * 64 + n) = make_float2(acc[mi][nj][0], acc[mi][nj][1]);
            *(float2*)(outp + (m0 + 8) * 64 + n) = make_float2(acc[mi][nj][2], acc[mi][nj][3]);
        }
    }
}

// ---------------- reduce split-K partials for G and t (vectorized) ------------
__global__ void reduceGT_kernel()
{
    int o4 = blockIdx.x * 256 + threadIdx.x;
    const int NG4 = BATCH * CHN * CHN / 4;
    if (o4 < NG4) {
        float4 s = make_float4(0.f, 0.f, 0.f, 0.f);
        for (int sl = 0; sl < NSLICE; sl++) {
            float4 v = ((const float4*)g_gpart)[(size_t)sl * NG4 + o4];
            s.x += v.x; s.y += v.y; s.z += v.z; s.w += v.w;
        }
        ((float4*)g_G)[o4] = s;
    } else {
        int e4 = o4 - NG4;
        const int NT4 = BATCH * CHN * 64 / 4;
        if (e4 >= NT4) return;
        float4 s = make_float4(0.f, 0.f, 0.f, 0.f);
        for (int sl = 0; sl < NSLICE; sl++) {
            float4 v = ((const float4*)g_tpart)[(size_t)sl * NT4 + e4];
            s.x += v.x; s.y += v.y; s.z += v.z; s.w += v.w;
        }
        ((float4*)g_t)[e4] = s;
    }
}

// ---------------- solve: [G | t] -> G^{-1} t, register-resident GJ -----------
__global__ __launch_bounds__(768) void solve_kernel()
{
    __shared__ float fcol[128];
    __shared__ float prow[192];
    __shared__ float pinv_s;
    const int b = blockIdx.x, tid = threadIdx.x;
    const int j = tid % 192, g = tid / 192;

    float mv[32];
    if (j < 128) {
#pragma unroll
        for (int i = 0; i < 32; i++)
            mv[i] = g_G[(size_t)b * CHN * CHN + (size_t)(g * 32 + i) * 128 + j];
    } else {
        int m = j - 128;
#pragma unroll
        for (int i = 0; i < 32; i++)
            mv[i] = g_t[((size_t)b * CHN + g * 32 + i) * 64 + m];
    }

    for (int p = 0; p < 128; p++) {
        const int gp = p >> 5, pi = p & 31;
        if (j == p) {
#pragma unroll
            for (int i = 0; i < 32; i++) fcol[g * 32 + i] = mv[i];
            if (g == gp) pinv_s = 1.0f / mv[pi];
        }
        __syncthreads();
        if (g == gp) prow[j] = mv[pi] * pinv_s;
        __syncthreads();
        if (j >= 128 || j > p) {
            float pr = prow[j];
#pragma unroll
            for (int i = 0; i < 32; i++) {
                int row = g * 32 + i;
                float v = mv[i] - fcol[row] * pr;
                mv[i] = (row == p) ? pr : v;
            }
        }
        __syncthreads();
    }

    if (j >= 128) {
        int m = j - 128;
#pragma unroll
        for (int i = 0; i < 32; i++)
            g_t2[((size_t)b * CHN + g * 32 + i) * 64 + m] = mv[i];
    }
}

// ---------------- proj via fp16 mma: out[m][n] = sum_c t2[c][m] V[c][n] ------
// A = t2^T fp16 in smem [64][136]; B = V interleaved (conv-style frags).
__global__ __launch_bounds__(256, 2) void projh_kernel(float* __restrict__ out)
{
    __shared__ __half st2h[64 * 136];
    __shared__ __half sVi[2][256 * 16];

    const int tid = threadIdx.x;
    const int lane = tid & 31;
    const int wid = tid >> 5;
    const int lq = lane >> 2;
    const int lr = lane & 3;
    const int b = blockIdx.y;
    const int n0cta = blockIdx.x * 256;
    const __half* Vi = g_feati + ((size_t)b * 8 * NPIX << 4);

    // t2 transpose fp16 into smem: st2h[m][c]
    for (int e = tid; e < 8192; e += 256) {
        int c = e >> 6, m = e & 63;
        st2h[m * 136 + c] = __float2half_rn(g_t2[(size_t)b * CHN * 64 + e]);
    }

    auto stageV = [&](int buf, int cc) {
        const __half* src = Vi + ((size_t)cc * NPIX << 4);
#pragma unroll
        for (int r = 0; r < 2; r++) {
            int px = (tid >> 1) + r * 128;
            int part = tid & 1;
            cp16(smem_u32(&sVi[buf][px * 16 + part * 8]),
                 src + (((size_t)(n0cta + px)) << 4) + part * 8);
        }
    };
    stageV(0, 0);
    CP_COMMIT();

    float acc[4][4][4];
#pragma unroll
    for (int mi = 0; mi < 4; mi++)
#pragma unroll
        for (int nj = 0; nj < 4; nj++)
#pragma unroll
            for (int e = 0; e < 4; e++) acc[mi][nj][e] = 0.f;

    for (int cc = 0; cc < 8; cc++) {
        if (cc < 7) {
            stageV((cc + 1) & 1, cc + 1);
            CP_COMMIT();
            CP_WAIT1();
        } else {
            CP_WAIT0();
        }
        __syncthreads();   // covers st2h on first iter + sVi buffer
        const uint32_t* s2 = (const uint32_t*)st2h;  // row stride 68 words
        const __half* sv = sVi[cc & 1];
        uint4 af[4];
#pragma unroll
        for (int mi = 0; mi < 4; mi++) {
            int m0 = mi * 16;
            af[mi].x = s2[(m0 + lq) * 68 + cc * 8 + lr];
            af[mi].y = s2[(m0 + lq + 8) * 68 + cc * 8 + lr];
            af[mi].z = s2[(m0 + lq) * 68 + cc * 8 + 4 + lr];
            af[mi].w = s2[(m0 + lq + 8) * 68 + cc * 8 + 4 + lr];
        }
#pragma unroll
        for (int nj = 0; nj < 4; nj++) {
            int n = wid * 32 + nj * 8 + lq;
            uint2 bv = *(const uint2*)(sv + n * 16 + lr * 4);
#pragma unroll
            for (int mi = 0; mi < 4; mi++) mma_f16(acc[mi][nj], af[mi], bv.x, bv.y);
        }
        __syncthreads();
    }

#pragma unroll
    for (int mi = 0; mi < 4; mi++) {
        int m0 = mi * 16 + lq;
#pragma unroll
        for (int nj = 0; nj < 4; nj++) {
            int n = n0cta + wid * 32 + nj * 8 + lr * 2;
            *(float2*)(out + ((size_t)(b * 64 + m0)) * NPIX + n) =
                make_float2(acc[mi][nj][0], acc[mi][nj][1]);
            *(float2*)(out + ((size_t)(b * 64 + m0 + 8)) * NPIX + n) =
                make_float2(acc[mi][nj][2], acc[mi][nj][3]);
        }
    }
}

// ---------------- launch -----------------------------------------------------
extern "C" void kernel_launch(void* const* d_in, const int* in_sizes, int n_in,
                              void* d_out, int out_size)
{
    const float* x1 = (const float*)d_in[0];
    const float* x2 = (const float*)d_in[1];
    const float* w1 = (const float*)d_in[2];
    const float* b1 = (const float*)d_in[3];
    const float* w2 = (const float*)d_in[4];
    const float* b2 = (const float*)d_in[5];
    const float* wi = (const float*)d_in[6];
    const float* bi = (const float*)d_in[7];
    float* out = (float*)d_out;

    uint32_t* wh1;  cudaGetSymbolAddress((void**)&wh1, g_wh1);
    uint32_t* wh2;  cudaGetSymbolAddress((void**)&wh2, g_wh2);
    uint32_t* wih;  cudaGetSymbolAddress((void**)&wih, g_wih);

    prep_repack_kernel<<<2200, 256>>>(x1, x2, w1, w2, wi, wh1, wh2, wih);

    dim3 cgrid(8, 16, 4);
    conv_fp16_kernel<true><<<cgrid, 256>>>(b1);
    gemm1x1h_kernel<<<cgrid, 256>>>(bi);
    conv_fp16_kernel<false><<<cgrid, 256>>>(b2);

    gemmGh_kernel<<<dim3(NSLICE, BATCH), 256>>>();
    gemmTh_kernel<<<dim3(NSLICE, BATCH), 256>>>();
    reduceGT_kernel<<<96, 256>>>();
    solve_kernel<<<BATCH, 768>>>();
    projh_kernel<<<dim3(64, BATCH), 256>>>(out);
}

// round 16
// speedup vs baseline: 1.0393x; 1.0393x over previous
#include <cuda_runtime.h>
#include <cuda_fp16.h>
#include <cstdint>
#include <cstddef>

#define NPIX 16384
#define CHN 128
#define BATCH 4
#define NSLICE 64

// ---------------- scratch (device globals; no allocation allowed) -------------
__device__ __align__(16) __half g_cath[BATCH * 8 * NPIX * 16];   // cat, fp16 interleaved
__device__ __align__(16) __half g_buf1h[BATCH * 8 * NPIX * 16];  // conv1 out, interleaved
__device__ __align__(16) __half g_feath[BATCH * CHN * NPIX];     // feat fp16 [c][n]
__device__ __align__(16) __half g_x1h[BATCH * 64 * NPIX];        // x1 fp16 [c][n]
__device__ float g_gpart[NSLICE * BATCH * CHN * CHN];
__device__ float g_G[BATCH * CHN * CHN];
__device__ float g_tpart[NSLICE * BATCH * CHN * 64];
__device__ float g_t[BATCH * CHN * 64];               // reduced t
__device__ float g_t2[BATCH * CHN * 64];              // G^{-1} t
// fp16 conv weight fragments: [chunk8][tap9][mfrag8][lane32] uint4
__device__ uint32_t g_wh1[8 * 9 * 8 * 32 * 4];
__device__ uint32_t g_wh2[8 * 9 * 8 * 32 * 4];
__device__ uint32_t g_wih[8 * 8 * 32 * 4];            // 1x1 fp16 fragments

__device__ __forceinline__ float leakyf(float v) { return v >= 0.f ? v : 0.2f * v; }

__device__ __forceinline__ void mma_f16(float* acc, const uint4& a, uint32_t b0, uint32_t b1) {
    asm volatile(
        "mma.sync.aligned.m16n8k16.row.col.f32.f16.f16.f32 "
        "{%0,%1,%2,%3}, {%4,%5,%6,%7}, {%8,%9}, {%0,%1,%2,%3};"
        : "+f"(acc[0]), "+f"(acc[1]), "+f"(acc[2]), "+f"(acc[3])
        : "r"(a.x), "r"(a.y), "r"(a.z), "r"(a.w), "r"(b0), "r"(b1));
}

__device__ __forceinline__ uint32_t smem_u32(const void* p) {
    return (uint32_t)__cvta_generic_to_shared(p);
}
__device__ __forceinline__ void cp16(uint32_t s, const void* g) {
    asm volatile("cp.async.cg.shared.global [%0], [%1], 16;" :: "r"(s), "l"(g));
}
__device__ __forceinline__ void cp16z(uint32_t s, const void* g, int valid16) {
    asm volatile("cp.async.cg.shared.global [%0], [%1], 16, %2;"
                 :: "r"(s), "l"(g), "r"(valid16));
}
#define CP_COMMIT() asm volatile("cp.async.commit_group;")
#define CP_WAIT1() asm volatile("cp.async.wait_group 1;")
#define CP_WAIT0() asm volatile("cp.async.wait_group 0;")

__device__ __forceinline__ uint32_t pack_h2(float lo, float hi) {
    __half2 h = __floats2half2_rn(lo, hi);
    return *(uint32_t*)&h;
}
__device__ __forceinline__ uint32_t pack_hh(__half lo, __half hi) {
    __half2 h = __halves2half2(lo, hi);
    return *(uint32_t*)&h;
}
// permuted ic position inside 16-ic group (matches m16n8k16 B-fragment order)
__device__ __forceinline__ int icpos(int k) {
    return (k < 8) ? ((k >> 1) * 4 + (k & 1)) : (((k - 8) >> 1) * 4 + 2 + (k & 1));
}

// ---------------- prep (smem transpose, coalesced) + weight repack ------------
__device__ __forceinline__ void repack_wh(const float* __restrict__ w, uint4* __restrict__ out,
                                          int idx)
{
    int lane = idx & 31;
    int t = idx >> 5;
    int mf = t & 7;
    int t2 = t >> 3;
    int tap = t2 % 9;
    int chunk = t2 / 9;
    int lq = lane >> 2, lr = lane & 3;
    int oc0 = mf * 16 + lq, oc1 = oc0 + 8;
    int kb = chunk * 16;
    uint4 o;
    o.x = pack_h2(w[((size_t)oc0 * CHN + kb + 2 * lr) * 9 + tap],
                  w[((size_t)oc0 * CHN + kb + 2 * lr + 1) * 9 + tap]);
    o.y = pack_h2(w[((size_t)oc1 * CHN + kb + 2 * lr) * 9 + tap],
                  w[((size_t)oc1 * CHN + kb + 2 * lr + 1) * 9 + tap]);
    o.z = pack_h2(w[((size_t)oc0 * CHN + kb + 8 + 2 * lr) * 9 + tap],
                  w[((size_t)oc0 * CHN + kb + 9 + 2 * lr) * 9 + tap]);
    o.w = pack_h2(w[((size_t)oc1 * CHN + kb + 8 + 2 * lr) * 9 + tap],
                  w[((size_t)oc1 * CHN + kb + 9 + 2 * lr) * 9 + tap]);
    out[idx] = o;
}

__global__ void prep_repack_kernel(const float* __restrict__ x1, const float* __restrict__ x2,
                                   const float* __restrict__ w1, const float* __restrict__ w2,
                                   const float* __restrict__ wi,
                                   uint32_t* __restrict__ wh1, uint32_t* __restrict__ wh2,
                                   uint32_t* __restrict__ wih)
{
    __shared__ __half sT[16][264];
    int bx = blockIdx.x;
    int tid = threadIdx.x;
    if (bx < 2048) {
        int b = bx >> 9;
        int rem = bx & 511;
        int chunk = rem >> 6;
        int n0 = (rem & 63) * 256;
#pragma unroll
        for (int k = 0; k < 16; k++) {
            int ic = chunk * 16 + k;
            const float* src = (ic < 64) ? x1 + ((size_t)(b * 64 + ic) << 14)
                                         : x2 + ((size_t)(b * 64 + ic - 64) << 14);
            sT[k][tid] = __float2half_rn(src[n0 + tid]);
        }
        __syncthreads();
        __half v[16];
#pragma unroll
        for (int k = 0; k < 16; k++) v[icpos(k)] = sT[k][tid];
        __half* dst = g_cath + (((size_t)(b * 8 + chunk) * NPIX + n0 + tid) << 4);
        *(uint4*)dst = *(uint4*)&v[0];
        *(uint4*)(dst + 8) = *(uint4*)&v[8];
        if (chunk < 4) {  // fp16 copy of x1 for gemmT (coalesced)
#pragma unroll
            for (int k = 0; k < 16; k++)
                g_x1h[((size_t)(b * 64 + chunk * 16 + k)) * NPIX + n0 + tid] = sT[k][tid];
        }
    } else if (bx < 2120) {
        int idx = (bx - 2048) * 256 + tid;
        if (idx < 18432) repack_wh(w1, (uint4*)wh1, idx);
    } else if (bx < 2192) {
        int idx = (bx - 2120) * 256 + tid;
        if (idx < 18432) repack_wh(w2, (uint4*)wh2, idx);
    } else {
        int idx = (bx - 2192) * 256 + tid;
        if (idx >= 2048) return;
        int lane = idx & 31;
        int t = idx >> 5;
        int mf = t & 7;
        int chunk = t >> 3;
        int lq = lane >> 2, lr = lane & 3;
        int oc0 = mf * 16 + lq, oc1 = oc0 + 8;
        int kb = chunk * 16;
        uint4 o;
        o.x = pack_h2(wi[(size_t)oc0 * CHN + kb + 2 * lr], wi[(size_t)oc0 * CHN + kb + 2 * lr + 1]);
        o.y = pack_h2(wi[(size_t)oc1 * CHN + kb + 2 * lr], wi[(size_t)oc1 * CHN + kb + 2 * lr + 1]);
        o.z = pack_h2(wi[(size_t)oc0 * CHN + kb + 8 + 2 * lr], wi[(size_t)oc0 * CHN + kb + 9 + 2 * lr]);
        o.w = pack_h2(wi[(size_t)oc1 * CHN + kb + 8 + 2 * lr], wi[(size_t)oc1 * CHN + kb + 9 + 2 * lr]);
        ((uint4*)wih)[idx] = o;
    }
}

// ---------------- conv 3x3 via fp16 m16n8k16, weights via direct LDG ---------
template <bool FIRST>
__global__ __launch_bounds__(256, 2) void conv_fp16_kernel(const float* __restrict__ bias)
{
    __shared__ __half sIn[2][2880];            // [10 rows][18 px][16 icperm]

    const int tid = threadIdx.x;
    const int lane = tid & 31;
    const int wid = tid >> 5;
    const int warpM = wid & 3;
    const int warpN = wid >> 2;
    const int lq = lane >> 2;
    const int lr = lane & 3;
    const int b = blockIdx.z;
    const int r0 = blockIdx.y * 8;
    const int c0 = blockIdx.x * 16;

    float acc[2][8][4];
#pragma unroll
    for (int m = 0; m < 2; m++)
#pragma unroll
        for (int j = 0; j < 8; j++)
#pragma unroll
            for (int e = 0; e < 4; e++) acc[m][j][e] = 0.f;

    const uint4* wsrc = (const uint4*)(FIRST ? g_wh1 : g_wh2);
    const uint4* wwarp0 = wsrc + (warpM * 2 + 0) * 32 + lane;
    const uint4* wwarp1 = wsrc + (warpM * 2 + 1) * 32 + lane;
    const __half* ibase = (FIRST ? g_cath : g_buf1h) + ((size_t)b * 8 * NPIX << 4);

    // hoisted staging descriptors
    uint32_t sOff0 = 0, sOff1 = 0;
    size_t gOff0 = 0, gOff1 = 0;
    int vld0 = 0, vld1 = 0;
    {
        int i = tid;
        int row = i / 36;
        int p2 = i - row * 36;
        int px = p2 >> 1, hp = p2 & 1;
        int gr = r0 - 1 + row, gc = c0 - 1 + px;
        vld0 = (((unsigned)gr < 128u) && ((unsigned)gc < 128u)) ? 16 : 0;
        gOff0 = (((size_t)(vld0 ? gr * 128 + gc : 0)) << 4) + hp * 8;
        sOff0 = (uint32_t)(row * 288 + px * 16 + hp * 8);
        i = tid + 256;
        if (i < 360) {
            row = i / 36;
            p2 = i - row * 36;
            px = p2 >> 1; hp = p2 & 1;
            gr = r0 - 1 + row; gc = c0 - 1 + px;
            vld1 = (((unsigned)gr < 128u) && ((unsigned)gc < 128u)) ? 16 : 0;
            gOff1 = (((size_t)(vld1 ? gr * 128 + gc : 0)) << 4) + hp * 8;
            sOff1 = (uint32_t)(row * 288 + px * 16 + hp * 8);
        }
    }
    const bool has1 = (tid + 256) < 360;

    auto stin = [&](int buf, int cc) {
        const __half* src = ibase + ((size_t)cc * NPIX << 4);
        uint32_t sb = smem_u32(sIn[buf]);
        cp16z(sb + sOff0 * 2, src + gOff0, vld0);
        if (has1) cp16z(sb + sOff1 * 2, src + gOff1, vld1);
    };

    stin(0, 0);
    CP_COMMIT();

    uint4 a0 = __ldg(wwarp0);
    uint4 a1 = __ldg(wwarp1);

    for (int cc = 0; cc < 8; cc++) {
        if (cc < 7) {
            stin((cc + 1) & 1, cc + 1);
            CP_COMMIT();
            CP_WAIT1();
        } else {
            CP_WAIT0();
        }
        __syncthreads();

        const __half* ib = sIn[cc & 1];
#pragma unroll
        for (int tap = 0; tap < 9; tap++) {
            const int dr = tap / 3, dc = tap % 3;
            uint2 bv[8];
#pragma unroll
            for (int j = 0; j < 8; j++) {
                int row = warpN * 4 + (j >> 1) + dr;
                int slot = (j & 1) * 8 + lq + dc;
                bv[j] = *(const uint2*)(ib + row * 288 + slot * 16 + lr * 4);
            }
            int s = cc * 9 + tap;
            uint4 na0, na1;
            if (s < 71) {
                na0 = __ldg(wwarp0 + (s + 1) * 256);
                na1 = __ldg(wwarp1 + (s + 1) * 256);
            }
#pragma unroll
            for (int j = 0; j < 8; j++) {
                mma_f16(acc[0][j], a0, bv[j].x, bv[j].y);
                mma_f16(acc[1][j], a1, bv[j].x, bv[j].y);
            }
            if (s < 71) { a0 = na0; a1 = na1; }
        }
        __syncthreads();
    }

    // ---- epilogue ----
#pragma unroll
    for (int m = 0; m < 2; m++) {
        int oc = warpM * 32 + m * 16 + lq;
        float bv0 = bias[oc], bv1 = bias[oc + 8];
        if (FIRST) {
            const int chunk = warpM * 2 + m;
            const int ip0 = icpos(lq), ip1 = icpos(lq + 8);
            __half* hb = g_buf1h + (((size_t)(b * 8 + chunk) * NPIX) << 4);
#pragma unroll
            for (int j = 0; j < 8; j++) {
                int pix = (r0 + warpN * 4 + (j >> 1)) * 128 + c0 + (j & 1) * 8 + lr * 2;
                __half* p = hb + ((size_t)pix << 4);
                p[ip0] = __float2half_rn(leakyf(acc[m][j][0] + bv0));
                p[16 + ip0] = __float2half_rn(leakyf(acc[m][j][1] + bv0));
                p[ip1] = __float2half_rn(leakyf(acc[m][j][2] + bv1));
                p[16 + ip1] = __float2half_rn(leakyf(acc[m][j][3] + bv1));
            }
        } else {
            __half* hf0 = g_feath + ((size_t)(b * CHN + oc)) * NPIX;
            __half* hf1 = hf0 + (size_t)8 * NPIX;
#pragma unroll
            for (int j = 0; j < 8; j++) {
                int pix = (r0 + warpN * 4 + (j >> 1)) * 128 + c0 + (j & 1) * 8 + lr * 2;
                __half2 q0 = *(__half2*)(hf0 + pix);
                __half2 q1 = *(__half2*)(hf1 + pix);
                float v00 = __low2float(q0) + leakyf(acc[m][j][0] + bv0);
                float v01 = __high2float(q0) + leakyf(acc[m][j][1] + bv0);
                float v10 = __low2float(q1) + leakyf(acc[m][j][2] + bv1);
                float v11 = __high2float(q1) + leakyf(acc[m][j][3] + bv1);
                *(__half2*)(hf0 + pix) = __floats2half2_rn(v00, v01);
                *(__half2*)(hf1 + pix) = __floats2half2_rn(v10, v11);
            }
        }
    }
}

// ---------------- 1x1 conv via fp16 m16n8k16 (reuses g_cath) ------------------
__global__ __launch_bounds__(256) void gemm1x1h_kernel(const float* __restrict__ bi)
{
    __shared__ uint4 sW1[2][256];
    __shared__ __half sB[2][2048];

    const int tid = threadIdx.x;
    const int lane = tid & 31;
    const int wid = tid >> 5;
    const int warpM = wid & 3;
    const int warpN = wid >> 2;
    const int lq = lane >> 2;
    const int lr = lane & 3;
    const int b = blockIdx.z;
    const int r0 = blockIdx.y * 8;
    const int c0 = blockIdx.x * 16;

    float acc[2][8][4];
#pragma unroll
    for (int m = 0; m < 2; m++)
#pragma unroll
        for (int j = 0; j < 8; j++)
#pragma unroll
            for (int e = 0; e < 4; e++) acc[m][j][e] = 0.f;

    const __half* ibase = g_cath + ((size_t)b * 8 * NPIX << 4);

    auto stage = [&](int buf, int cc) {
        int hp = tid & 1;
        int pl = tid >> 1;
        int row = pl >> 4, px = pl & 15;
        int pix = (r0 + row) * 128 + c0 + px;
        cp16(smem_u32(&sB[buf][(row * 16 + px) * 16 + hp * 8]),
             ibase + ((size_t)cc * NPIX << 4) + ((size_t)pix << 4) + hp * 8);
        cp16(smem_u32(&sW1[buf][tid]), ((const uint4*)g_wih) + cc * 256 + tid);
    };

    stage(0, 0);
    CP_COMMIT();

    for (int cc = 0; cc < 8; cc++) {
        if (cc < 7) {
            stage((cc + 1) & 1, cc + 1);
            CP_COMMIT();
            CP_WAIT1();
        } else {
            CP_WAIT0();
        }
        __syncthreads();

        uint4 a0 = sW1[cc & 1][(warpM * 2 + 0) * 32 + lane];
        uint4 a1 = sW1[cc & 1][(warpM * 2 + 1) * 32 + lane];
        const __half* ib = sB[cc & 1];
        uint2 bv[8];
#pragma unroll
        for (int j = 0; j < 8; j++) {
            int row = warpN * 4 + (j >> 1);
            int slot = (j & 1) * 8 + lq;
            bv[j] = *(const uint2*)(ib + (row * 16 + slot) * 16 + lr * 4);
        }
#pragma unroll
        for (int j = 0; j < 8; j++) {
            mma_f16(acc[0][j], a0, bv[j].x, bv[j].y);
            mma_f16(acc[1][j], a1, bv[j].x, bv[j].y);
        }
        __syncthreads();
    }

#pragma unroll
    for (int m = 0; m < 2; m++) {
        int oc = warpM * 32 + m * 16 + lq;
        float b0 = bi[oc], b1 = bi[oc + 8];
        __half* hf0 = g_feath + ((size_t)(b * CHN + oc)) * NPIX;
        __half* hf1 = hf0 + (size_t)8 * NPIX;
#pragma unroll
        for (int j = 0; j < 8; j++) {
            int pix = (r0 + warpN * 4 + (j >> 1)) * 128 + c0 + (j & 1) * 8 + lr * 2;
            *(__half2*)(hf0 + pix) = __floats2half2_rn(acc[m][j][0] + b0, acc[m][j][1] + b0);
            *(__half2*)(hf1 + pix) = __floats2half2_rn(acc[m][j][2] + b1, acc[m][j][3] + b1);
        }
    }
}

// ---------------- G = V V^T via fp16 mma, split-K -----------------------------
// (Projection invariant to V row scaling; reference L1 normalization skipped.)
__global__ __launch_bounds__(256, 2) void gemmGh_kernel()
{
    __shared__ __half sV[2][128 * 24];   // stride 24 halves = 12 words, conflict-free
    const int tid = threadIdx.x;
    const int lane = tid & 31;
    const int wid = tid >> 5;
    const int warpM = wid & 3;
    const int warpN = wid >> 2;
    const int lq = lane >> 2;
    const int lr = lane & 3;
    const int slice = blockIdx.x, b = blockIdx.y;
    const __half* base = g_feath + (size_t)b * CHN * NPIX;
    const int k0g = slice * 256;

    float acc[2][8][4];
#pragma unroll
    for (int mi = 0; mi < 2; mi++)
#pragma unroll
        for (int nj = 0; nj < 8; nj++)
#pragma unroll
            for (int e = 0; e < 4; e++) acc[mi][nj][e] = 0.f;

    auto stage = [&](int buf, int kc) {
        int kk = k0g + kc * 16;
        int c = tid >> 1, part = tid & 1;
        cp16(smem_u32(&sV[buf][c * 24 + part * 8]), base + (size_t)c * NPIX + kk + part * 8);
    };
    stage(0, 0);
    CP_COMMIT();

    for (int kc = 0; kc < 16; kc++) {
        if (kc < 15) {
            stage((kc + 1) & 1, kc + 1);
            CP_COMMIT();
            CP_WAIT1();
        } else {
            CP_WAIT0();
        }
        __syncthreads();
        const uint32_t* sv = (const uint32_t*)sV[kc & 1];   // row stride 12 words
        uint4 af[2];
#pragma unroll
        for (int mi = 0; mi < 2; mi++) {
            int m0 = warpM * 32 + mi * 16;
            af[mi].x = sv[(m0 + lq) * 12 + lr];
            af[mi].y = sv[(m0 + lq + 8) * 12 + lr];
            af[mi].z = sv[(m0 + lq) * 12 + 4 + lr];
            af[mi].w = sv[(m0 + lq + 8) * 12 + 4 + lr];
        }
#pragma unroll
        for (int nj = 0; nj < 8; nj++) {
            int n0 = warpN * 64 + nj * 8;
            uint32_t b0 = sv[(n0 + lq) * 12 + lr];
            uint32_t b1 = sv[(n0 + lq) * 12 + 4 + lr];
            mma_f16(acc[0][nj], af[0], b0, b1);
            mma_f16(acc[1][nj], af[1], b0, b1);
        }
        __syncthreads();
    }

    float* outp = g_gpart + ((size_t)slice * BATCH + b) * CHN * CHN;
#pragma unroll
    for (int mi = 0; mi < 2; mi++) {
        int m0 = warpM * 32 + mi * 16 + lq;
#pragma unroll
        for (int nj = 0; nj < 8; nj++) {
            int n = warpN * 64 + nj * 8 + lr * 2;
            *(float2*)(outp + m0 * 128 + n) = make_float2(acc[mi][nj][0], acc[mi][nj][1]);
            *(float2*)(outp + (m0 + 8) * 128 + n) = make_float2(acc[mi][nj][2], acc[mi][nj][3]);
        }
    }
}

// ---------------- t = V @ x1^T via fp16 mma, split-K --------------------------
__global__ __launch_bounds__(256, 2) void gemmTh_kernel()
{
    __shared__ __half sV[2][128 * 24];
    __shared__ __half sX[2][64 * 24];
    const int tid = threadIdx.x;
    const int lane = tid & 31;
    const int wid = tid >> 5;
    const int warpM = wid & 3;
    const int warpN = wid >> 2;
    const int lq = lane >> 2;
    const int lr = lane & 3;
    const int slice = blockIdx.x, b = blockIdx.y;
    const __half* vbase = g_feath + (size_t)b * CHN * NPIX;
    const __half* xbase = g_x1h + (size_t)b * 64 * NPIX;
    const int k0g = slice * 256;

    float acc[2][4][4];
#pragma unroll
    for (int mi = 0; mi < 2; mi++)
#pragma unroll
        for (int nj = 0; nj < 4; nj++)
#pragma unroll
            for (int e = 0; e < 4; e++) acc[mi][nj][e] = 0.f;

    auto stage = [&](int buf, int kc) {
        int kk = k0g + kc * 16;
        int c = tid >> 1, part = tid & 1;
        cp16(smem_u32(&sV[buf][c * 24 + part * 8]), vbase + (size_t)c * NPIX + kk + part * 8);
        if (tid < 128)
            cp16(smem_u32(&sX[buf][c * 24 + part * 8]), xbase + (size_t)c * NPIX + kk + part * 8);
    };
    stage(0, 0);
    CP_COMMIT();

    for (int kc = 0; kc < 16; kc++) {
        if (kc < 15) {
            stage((kc + 1) & 1, kc + 1);
            CP_COMMIT();
            CP_WAIT1();
        } else {
            CP_WAIT0();
        }
        __syncthreads();
        const uint32_t* sv = (const uint32_t*)sV[kc & 1];
        const uint32_t* sx = (const uint32_t*)sX[kc & 1];
        uint4 af[2];
#pragma unroll
        for (int mi = 0; mi < 2; mi++) {
            int m0 = warpM * 32 + mi * 16;
            af[mi].x = sv[(m0 + lq) * 12 + lr];
            af[mi].y = sv[(m0 + lq + 8) * 12 + lr];
            af[mi].z = sv[(m0 + lq) * 12 + 4 + lr];
            af[mi].w = sv[(m0 + lq + 8) * 12 + 4 + lr];
        }
#pragma unroll
        for (int nj = 0; nj < 4; nj++) {
            int n0 = warpN * 32 + nj * 8;
            uint32_t b0 = sx[(n0 + lq) * 12 + lr];
            uint32_t b1 = sx[(n0 + lq) * 12 + 4 + lr];
            mma_f16(acc[0][nj], af[0], b0, b1);
            mma_f16(acc[1][nj], af[1], b0, b1);
        }
        __syncthreads();
    }

    float* outp = g_tpart + ((size_t)slice * BATCH + b) * CHN * 64;
#pragma unroll
    for (int mi = 0; mi < 2; mi++) {
        int m0 = warpM * 32 + mi * 16 + lq;
#pragma unroll
        for (int nj = 0; nj < 4; nj++) {
            int n = warpN * 32 + nj * 8 + lr * 2;
            *(float2*)(outp + m0 * 64 + n) = make_float2(acc[mi][nj][0], acc[mi][nj][1]);
            *(float2*)(outp + (m0 + 8) * 64 + n) = make_float2(acc[mi][nj][2], acc[mi][nj][3]);
        }
    }
}

// ---------------- reduce split-K partials for G and t (vectorized) ------------
__global__ void reduceGT_kernel()
{
    int o4 = blockIdx.x * 256 + threadIdx.x;
    const int NG4 = BATCH * CHN * CHN / 4;
    if (o4 < NG4) {
        float4 s = make_float4(0.f, 0.f, 0.f, 0.f);
        for (int sl = 0; sl < NSLICE; sl++) {
            float4 v = ((const float4*)g_gpart)[(size_t)sl * NG4 + o4];
            s.x += v.x; s.y += v.y; s.z += v.z; s.w += v.w;
        }
        ((float4*)g_G)[o4] = s;
    } else {
        int e4 = o4 - NG4;
        const int NT4 = BATCH * CHN * 64 / 4;
        if (e4 >= NT4) return;
        float4 s = make_float4(0.f, 0.f, 0.f, 0.f);
        for (int sl = 0; sl < NSLICE; sl++) {
            float4 v = ((const float4*)g_tpart)[(size_t)sl * NT4 + e4];
            s.x += v.x; s.y += v.y; s.z += v.z; s.w += v.w;
        }
        ((float4*)g_t)[e4] = s;
    }
}

// ---------------- solve: [G | t] -> G^{-1} t, register-resident GJ -----------
__global__ __launch_bounds__(768) void solve_kernel()
{
    __shared__ float fcol[128];
    __shared__ float prow[192];
    __shared__ float pinv_s;
    const int b = blockIdx.x, tid = threadIdx.x;
    const int j = tid % 192, g = tid / 192;

    float mv[32];
    if (j < 128) {
#pragma unroll
        for (int i = 0; i < 32; i++)
            mv[i] = g_G[(size_t)b * CHN * CHN + (size_t)(g * 32 + i) * 128 + j];
    } else {
        int m = j - 128;
#pragma unroll
        for (int i = 0; i < 32; i++)
            mv[i] = g_t[((size_t)b * CHN + g * 32 + i) * 64 + m];
    }

    for (int p = 0; p < 128; p++) {
        const int gp = p >> 5, pi = p & 31;
        if (j == p) {
#pragma unroll
            for (int i = 0; i < 32; i++) fcol[g * 32 + i] = mv[i];
            if (g == gp) pinv_s = 1.0f / mv[pi];
        }
        __syncthreads();
        if (g == gp) prow[j] = mv[pi] * pinv_s;
        __syncthreads();
        if (j >= 128 || j > p) {
            float pr = prow[j];
#pragma unroll
            for (int i = 0; i < 32; i++) {
                int row = g * 32 + i;
                float v = mv[i] - fcol[row] * pr;
                mv[i] = (row == p) ? pr : v;
            }
        }
        __syncthreads();
    }

    if (j >= 128) {
        int m = j - 128;
#pragma unroll
        for (int i = 0; i < 32; i++)
            g_t2[((size_t)b * CHN + g * 32 + i) * 64 + m] = mv[i];
    }
}

// ---------------- proj via fp16 mma: out[m][n] = sum_c t2[c][m] V[c][n] ------
// A = t2^T fp16 in smem [64][136]; B staged planar from g_feath [16c][264n].
__global__ __launch_bounds__(256, 2) void projh_kernel(float* __restrict__ out)
{
    __shared__ __half st2h[64 * 136];
    __shared__ __half sVt[2][16 * 264];

    const int tid = threadIdx.x;
    const int lane = tid & 31;
    const int wid = tid >> 5;
    const int lq = lane >> 2;
    const int lr = lane & 3;
    const int b = blockIdx.y;
    const int n0cta = blockIdx.x * 256;
    const __half* Vb = g_feath + (size_t)b * CHN * NPIX;

    // t2 transpose fp16 into smem: st2h[m][c]
    for (int e = tid; e < 8192; e += 256) {
        int c = e >> 6, m = e & 63;
        st2h[m * 136 + c] = __float2half_rn(g_t2[(size_t)b * CHN * 64 + e]);
    }

    // stage 16 channels x 256 px from planar feat (coalesced; 32 cp16/round, 2/thread)
    auto stageV = [&](int buf, int cc) {
        int row = tid >> 4, part = tid & 15;  // 16 rows x 16 parts of 16 halves... 256 px = 32 x 8h
        // each row = 256 halves = 32 cp16; 256 threads / 16 rows = 16 per row -> 2 cp16 each
        const __half* src = Vb + (size_t)(cc * 16 + row) * NPIX + n0cta;
        cp16(smem_u32(&sVt[buf][row * 264 + part * 8]), src + part * 8);
        cp16(smem_u32(&sVt[buf][row * 264 + 128 + part * 8]), src + 128 + part * 8);
    };
    stageV(0, 0);
    CP_COMMIT();

    float acc[4][4][4];
#pragma unroll
    for (int mi = 0; mi < 4; mi++)
#pragma unroll
        for (int nj = 0; nj < 4; nj++)
#pragma unroll
            for (int e = 0; e < 4; e++) acc[mi][nj][e] = 0.f;

    for (int cc = 0; cc < 8; cc++) {
        if (cc < 7) {
            stageV((cc + 1) & 1, cc + 1);
            CP_COMMIT();
            CP_WAIT1();
        } else {
            CP_WAIT0();
        }
        __syncthreads();   // covers st2h on first iter + sVt buffer
        const uint32_t* s2 = (const uint32_t*)st2h;  // row stride 68 words
        const __half* sv = sVt[cc & 1];
        uint4 af[4];
#pragma unroll
        for (int mi = 0; mi < 4; mi++) {
            int m0 = mi * 16;
            af[mi].x = s2[(m0 + lq) * 68 + cc * 8 + lr];
            af[mi].y = s2[(m0 + lq + 8) * 68 + cc * 8 + lr];
            af[mi].z = s2[(m0 + lq) * 68 + cc * 8 + 4 + lr];
            af[mi].w = s2[(m0 + lq + 8) * 68 + cc * 8 + 4 + lr];
        }
#pragma unroll
        for (int nj = 0; nj < 4; nj++) {
            int n = wid * 32 + nj * 8 + lq;
            uint32_t b0 = pack_hh(sv[(2 * lr) * 264 + n], sv[(2 * lr + 1) * 264 + n]);
            uint32_t b1 = pack_hh(sv[(2 * lr + 8) * 264 + n], sv[(2 * lr + 9) * 264 + n]);
#pragma unroll
            for (int mi = 0; mi < 4; mi++) mma_f16(acc[mi][nj], af[mi], b0, b1);
        }
        __syncthreads();
    }

#pragma unroll
    for (int mi = 0; mi < 4; mi++) {
        int m0 = mi * 16 + lq;
#pragma unroll
        for (int nj = 0; nj < 4; nj++) {
            int n = n0cta + wid * 32 + nj * 8 + lr * 2;
            *(float2*)(out + ((size_t)(b * 64 + m0)) * NPIX + n) =
                make_float2(acc[mi][nj][0], acc[mi][nj][1]);
            *(float2*)(out + ((size_t)(b * 64 + m0 + 8)) * NPIX + n) =
                make_float2(acc[mi][nj][2], acc[mi][nj][3]);
        }
    }
}

// ---------------- launch -----------------------------------------------------
extern "C" void kernel_launch(void* const* d_in, const int* in_sizes, int n_in,
                              void* d_out, int out_size)
{
    const float* x1 = (const float*)d_in[0];
    const float* x2 = (const float*)d_in[1];
    const float* w1 = (const float*)d_in[2];
    const float* b1 = (const float*)d_in[3];
    const float* w2 = (const float*)d_in[4];
    const float* b2 = (const float*)d_in[5];
    const float* wi = (const float*)d_in[6];
    const float* bi = (const float*)d_in[7];
    float* out = (float*)d_out;

    uint32_t* wh1;  cudaGetSymbolAddress((void**)&wh1, g_wh1);
    uint32_t* wh2;  cudaGetSymbolAddress((void**)&wh2, g_wh2);
    uint32_t* wih;  cudaGetSymbolAddress((void**)&wih, g_wih);

    prep_repack_kernel<<<2200, 256>>>(x1, x2, w1, w2, wi, wh1, wh2, wih);

    dim3 cgrid(8, 16, 4);
    conv_fp16_kernel<true><<<cgrid, 256>>>(b1);
    gemm1x1h_kernel<<<cgrid, 256>>>(bi);
    conv_fp16_kernel<false><<<cgrid, 256>>>(b2);

    gemmGh_kernel<<<dim3(NSLICE, BATCH), 256>>>();
    gemmTh_kernel<<<dim3(NSLICE, BATCH), 256>>>();
    reduceGT_kernel<<<96, 256>>>();
    solve_kernel<<<BATCH, 768>>>();
    projh_kernel<<<dim3(64, BATCH), 256>>>(out);
}

// round 17
// speedup vs baseline: 1.0602x; 1.0201x over previous
#include <cuda_runtime.h>
#include <cuda_fp16.h>
#include <cstdint>
#include <cstddef>

#define NPIX 16384
#define CHN 128
#define BATCH 4
#define NSLICE 64

// ---------------- scratch (device globals; no allocation allowed) -------------
__device__ __align__(16) __half g_cath[BATCH * 8 * NPIX * 16];   // cat, fp16 interleaved
__device__ __align__(16) __half g_buf1h[BATCH * 8 * NPIX * 16];  // conv1 out, interleaved
__device__ __align__(16) __half g_feath[BATCH * CHN * NPIX];     // feat fp16 [c][n]
__device__ __align__(16) __half g_x1h[BATCH * 64 * NPIX];        // x1 fp16 [c][n]
__device__ float g_gpart[NSLICE * BATCH * CHN * CHN];
__device__ float g_G[BATCH * CHN * CHN];
__device__ float g_tpart[NSLICE * BATCH * CHN * 64];
__device__ float g_t[BATCH * CHN * 64];               // reduced t
__device__ float g_t2[BATCH * CHN * 64];              // G^{-1} t
// fp16 conv weight fragments: [chunk8][tap9][mfrag8][lane32] uint4
__device__ uint32_t g_wh1[8 * 9 * 8 * 32 * 4];
__device__ uint32_t g_wh2[8 * 9 * 8 * 32 * 4];
__device__ uint32_t g_wih[8 * 8 * 32 * 4];            // 1x1 fp16 fragments

__device__ __forceinline__ float leakyf(float v) { return v >= 0.f ? v : 0.2f * v; }

__device__ __forceinline__ void mma_f16(float* acc, const uint4& a, uint32_t b0, uint32_t b1) {
    asm volatile(
        "mma.sync.aligned.m16n8k16.row.col.f32.f16.f16.f32 "
        "{%0,%1,%2,%3}, {%4,%5,%6,%7}, {%8,%9}, {%0,%1,%2,%3};"
        : "+f"(acc[0]), "+f"(acc[1]), "+f"(acc[2]), "+f"(acc[3])
        : "r"(a.x), "r"(a.y), "r"(a.z), "r"(a.w), "r"(b0), "r"(b1));
}

__device__ __forceinline__ uint32_t smem_u32(const void* p) {
    return (uint32_t)__cvta_generic_to_shared(p);
}
__device__ __forceinline__ void cp16(uint32_t s, const void* g) {
    asm volatile("cp.async.cg.shared.global [%0], [%1], 16;" :: "r"(s), "l"(g));
}
__device__ __forceinline__ void cp16z(uint32_t s, const void* g, int valid16) {
    asm volatile("cp.async.cg.shared.global [%0], [%1], 16, %2;"
                 :: "r"(s), "l"(g), "r"(valid16));
}
#define CP_COMMIT() asm volatile("cp.async.commit_group;")
#define CP_WAIT1() asm volatile("cp.async.wait_group 1;")
#define CP_WAIT0() asm volatile("cp.async.wait_group 0;")

__device__ __forceinline__ uint32_t pack_h2(float lo, float hi) {
    __half2 h = __floats2half2_rn(lo, hi);
    return *(uint32_t*)&h;
}
__device__ __forceinline__ uint32_t pack_hh(__half lo, __half hi) {
    __half2 h = __halves2half2(lo, hi);
    return *(uint32_t*)&h;
}
// permuted ic position inside 16-ic group (matches m16n8k16 B-fragment order)
__device__ __forceinline__ int icpos(int k) {
    return (k < 8) ? ((k >> 1) * 4 + (k & 1)) : (((k - 8) >> 1) * 4 + 2 + (k & 1));
}

// ---------------- prep (smem transpose, coalesced) + weight repack ------------
__device__ __forceinline__ void repack_wh(const float* __restrict__ w, uint4* __restrict__ out,
                                          int idx)
{
    int lane = idx & 31;
    int t = idx >> 5;
    int mf = t & 7;
    int t2 = t >> 3;
    int tap = t2 % 9;
    int chunk = t2 / 9;
    int lq = lane >> 2, lr = lane & 3;
    int oc0 = mf * 16 + lq, oc1 = oc0 + 8;
    int kb = chunk * 16;
    uint4 o;
    o.x = pack_h2(w[((size_t)oc0 * CHN + kb + 2 * lr) * 9 + tap],
                  w[((size_t)oc0 * CHN + kb + 2 * lr + 1) * 9 + tap]);
    o.y = pack_h2(w[((size_t)oc1 * CHN + kb + 2 * lr) * 9 + tap],
                  w[((size_t)oc1 * CHN + kb + 2 * lr + 1) * 9 + tap]);
    o.z = pack_h2(w[((size_t)oc0 * CHN + kb + 8 + 2 * lr) * 9 + tap],
                  w[((size_t)oc0 * CHN + kb + 9 + 2 * lr) * 9 + tap]);
    o.w = pack_h2(w[((size_t)oc1 * CHN + kb + 8 + 2 * lr) * 9 + tap],
                  w[((size_t)oc1 * CHN + kb + 9 + 2 * lr) * 9 + tap]);
    out[idx] = o;
}

__global__ void prep_repack_kernel(const float* __restrict__ x1, const float* __restrict__ x2,
                                   const float* __restrict__ w1, const float* __restrict__ w2,
                                   const float* __restrict__ wi,
                                   uint32_t* __restrict__ wh1, uint32_t* __restrict__ wh2,
                                   uint32_t* __restrict__ wih)
{
    __shared__ __half sT[16][264];
    int bx = blockIdx.x;
    int tid = threadIdx.x;
    if (bx < 2048) {
        int b = bx >> 9;
        int rem = bx & 511;
        int chunk = rem >> 6;
        int n0 = (rem & 63) * 256;
#pragma unroll
        for (int k = 0; k < 16; k++) {
            int ic = chunk * 16 + k;
            const float* src = (ic < 64) ? x1 + ((size_t)(b * 64 + ic) << 14)
                                         : x2 + ((size_t)(b * 64 + ic - 64) << 14);
            sT[k][tid] = __float2half_rn(src[n0 + tid]);
        }
        __syncthreads();
        __half v[16];
#pragma unroll
        for (int k = 0; k < 16; k++) v[icpos(k)] = sT[k][tid];
        __half* dst = g_cath + (((size_t)(b * 8 + chunk) * NPIX + n0 + tid) << 4);
        *(uint4*)dst = *(uint4*)&v[0];
        *(uint4*)(dst + 8) = *(uint4*)&v[8];
        if (chunk < 4) {  // fp16 copy of x1 for gemmT (coalesced)
#pragma unroll
            for (int k = 0; k < 16; k++)
                g_x1h[((size_t)(b * 64 + chunk * 16 + k)) * NPIX + n0 + tid] = sT[k][tid];
        }
    } else if (bx < 2120) {
        int idx = (bx - 2048) * 256 + tid;
        if (idx < 18432) repack_wh(w1, (uint4*)wh1, idx);
    } else if (bx < 2192) {
        int idx = (bx - 2120) * 256 + tid;
        if (idx < 18432) repack_wh(w2, (uint4*)wh2, idx);
    } else {
        int idx = (bx - 2192) * 256 + tid;
        if (idx >= 2048) return;
        int lane = idx & 31;
        int t = idx >> 5;
        int mf = t & 7;
        int chunk = t >> 3;
        int lq = lane >> 2, lr = lane & 3;
        int oc0 = mf * 16 + lq, oc1 = oc0 + 8;
        int kb = chunk * 16;
        uint4 o;
        o.x = pack_h2(wi[(size_t)oc0 * CHN + kb + 2 * lr], wi[(size_t)oc0 * CHN + kb + 2 * lr + 1]);
        o.y = pack_h2(wi[(size_t)oc1 * CHN + kb + 2 * lr], wi[(size_t)oc1 * CHN + kb + 2 * lr + 1]);
        o.z = pack_h2(wi[(size_t)oc0 * CHN + kb + 8 + 2 * lr], wi[(size_t)oc0 * CHN + kb + 9 + 2 * lr]);
        o.w = pack_h2(wi[(size_t)oc1 * CHN + kb + 8 + 2 * lr], wi[(size_t)oc1 * CHN + kb + 9 + 2 * lr]);
        ((uint4*)wih)[idx] = o;
    }
}

// ---------------- conv role (shared by convA and conv2) -----------------------
template <bool FIRST>
__device__ __forceinline__ void conv_role(char* smemRaw, int b, int r0, int c0,
                                          const float* __restrict__ bias)
{
    __half (*sIn)[2880] = (__half(*)[2880])smemRaw;

    const int tid = threadIdx.x;
    const int lane = tid & 31;
    const int wid = tid >> 5;
    const int warpM = wid & 3;
    const int warpN = wid >> 2;
    const int lq = lane >> 2;
    const int lr = lane & 3;

    float acc[2][8][4];
#pragma unroll
    for (int m = 0; m < 2; m++)
#pragma unroll
        for (int j = 0; j < 8; j++)
#pragma unroll
            for (int e = 0; e < 4; e++) acc[m][j][e] = 0.f;

    const uint4* wsrc = (const uint4*)(FIRST ? g_wh1 : g_wh2);
    const uint4* wwarp0 = wsrc + (warpM * 2 + 0) * 32 + lane;
    const uint4* wwarp1 = wsrc + (warpM * 2 + 1) * 32 + lane;
    const __half* ibase = (FIRST ? g_cath : g_buf1h) + ((size_t)b * 8 * NPIX << 4);

    // hoisted staging descriptors
    uint32_t sOff0 = 0, sOff1 = 0;
    size_t gOff0 = 0, gOff1 = 0;
    int vld0 = 0, vld1 = 0;
    {
        int i = tid;
        int row = i / 36;
        int p2 = i - row * 36;
        int px = p2 >> 1, hp = p2 & 1;
        int gr = r0 - 1 + row, gc = c0 - 1 + px;
        vld0 = (((unsigned)gr < 128u) && ((unsigned)gc < 128u)) ? 16 : 0;
        gOff0 = (((size_t)(vld0 ? gr * 128 + gc : 0)) << 4) + hp * 8;
        sOff0 = (uint32_t)(row * 288 + px * 16 + hp * 8);
        i = tid + 256;
        if (i < 360) {
            row = i / 36;
            p2 = i - row * 36;
            px = p2 >> 1; hp = p2 & 1;
            gr = r0 - 1 + row; gc = c0 - 1 + px;
            vld1 = (((unsigned)gr < 128u) && ((unsigned)gc < 128u)) ? 16 : 0;
            gOff1 = (((size_t)(vld1 ? gr * 128 + gc : 0)) << 4) + hp * 8;
            sOff1 = (uint32_t)(row * 288 + px * 16 + hp * 8);
        }
    }
    const bool has1 = (tid + 256) < 360;

    auto stin = [&](int buf, int cc) {
        const __half* src = ibase + ((size_t)cc * NPIX << 4);
        uint32_t sb = smem_u32(sIn[buf]);
        cp16z(sb + sOff0 * 2, src + gOff0, vld0);
        if (has1) cp16z(sb + sOff1 * 2, src + gOff1, vld1);
    };

    stin(0, 0);
    CP_COMMIT();

    uint4 a0 = __ldg(wwarp0);
    uint4 a1 = __ldg(wwarp1);

    for (int cc = 0; cc < 8; cc++) {
        if (cc < 7) {
            stin((cc + 1) & 1, cc + 1);
            CP_COMMIT();
            CP_WAIT1();
        } else {
            CP_WAIT0();
        }
        __syncthreads();

        const __half* ib = sIn[cc & 1];
#pragma unroll
        for (int tap = 0; tap < 9; tap++) {
            const int dr = tap / 3, dc = tap % 3;
            uint2 bv[8];
#pragma unroll
            for (int j = 0; j < 8; j++) {
                int row = warpN * 4 + (j >> 1) + dr;
                int slot = (j & 1) * 8 + lq + dc;
                bv[j] = *(const uint2*)(ib + row * 288 + slot * 16 + lr * 4);
            }
            int s = cc * 9 + tap;
            uint4 na0, na1;
            if (s < 71) {
                na0 = __ldg(wwarp0 + (s + 1) * 256);
                na1 = __ldg(wwarp1 + (s + 1) * 256);
            }
#pragma unroll
            for (int j = 0; j < 8; j++) {
                mma_f16(acc[0][j], a0, bv[j].x, bv[j].y);
                mma_f16(acc[1][j], a1, bv[j].x, bv[j].y);
            }
            if (s < 71) { a0 = na0; a1 = na1; }
        }
        __syncthreads();
    }

    // ---- epilogue ----
#pragma unroll
    for (int m = 0; m < 2; m++) {
        int oc = warpM * 32 + m * 16 + lq;
        float bv0 = bias[oc], bv1 = bias[oc + 8];
        if (FIRST) {
            const int chunk = warpM * 2 + m;
            const int ip0 = icpos(lq), ip1 = icpos(lq + 8);
            __half* hb = g_buf1h + (((size_t)(b * 8 + chunk) * NPIX) << 4);
#pragma unroll
            for (int j = 0; j < 8; j++) {
                int pix = (r0 + warpN * 4 + (j >> 1)) * 128 + c0 + (j & 1) * 8 + lr * 2;
                __half* p = hb + ((size_t)pix << 4);
                p[ip0] = __float2half_rn(leakyf(acc[m][j][0] + bv0));
                p[16 + ip0] = __float2half_rn(leakyf(acc[m][j][1] + bv0));
                p[ip1] = __float2half_rn(leakyf(acc[m][j][2] + bv1));
                p[16 + ip1] = __float2half_rn(leakyf(acc[m][j][3] + bv1));
            }
        } else {
            __half* hf0 = g_feath + ((size_t)(b * CHN + oc)) * NPIX;
            __half* hf1 = hf0 + (size_t)8 * NPIX;
#pragma unroll
            for (int j = 0; j < 8; j++) {
                int pix = (r0 + warpN * 4 + (j >> 1)) * 128 + c0 + (j & 1) * 8 + lr * 2;
                __half2 q0 = *(__half2*)(hf0 + pix);
                __half2 q1 = *(__half2*)(hf1 + pix);
                float v00 = __low2float(q0) + leakyf(acc[m][j][0] + bv0);
                float v01 = __high2float(q0) + leakyf(acc[m][j][1] + bv0);
                float v10 = __low2float(q1) + leakyf(acc[m][j][2] + bv1);
                float v11 = __high2float(q1) + leakyf(acc[m][j][3] + bv1);
                *(__half2*)(hf0 + pix) = __floats2half2_rn(v00, v01);
                *(__half2*)(hf1 + pix) = __floats2half2_rn(v10, v11);
            }
        }
    }
}

// ---------------- 1x1 role ----------------------------------------------------
__device__ __forceinline__ void onebyone_role(char* smemRaw, int b, int r0, int c0,
                                              const float* __restrict__ bi)
{
    uint4 (*sW1)[256] = (uint4(*)[256])smemRaw;          // 8192 B
    __half (*sB)[2048] = (__half(*)[2048])(smemRaw + 8192);  // 8192 B

    const int tid = threadIdx.x;
    const int lane = tid & 31;
    const int wid = tid >> 5;
    const int warpM = wid & 3;
    const int warpN = wid >> 2;
    const int lq = lane >> 2;
    const int lr = lane & 3;

    float acc[2][8][4];
#pragma unroll
    for (int m = 0; m < 2; m++)
#pragma unroll
        for (int j = 0; j < 8; j++)
#pragma unroll
            for (int e = 0; e < 4; e++) acc[m][j][e] = 0.f;

    const __half* ibase = g_cath + ((size_t)b * 8 * NPIX << 4);

    auto stage = [&](int buf, int cc) {
        int hp = tid & 1;
        int pl = tid >> 1;
        int row = pl >> 4, px = pl & 15;
        int pix = (r0 + row) * 128 + c0 + px;
        cp16(smem_u32(&sB[buf][(row * 16 + px) * 16 + hp * 8]),
             ibase + ((size_t)cc * NPIX << 4) + ((size_t)pix << 4) + hp * 8);
        cp16(smem_u32(&sW1[buf][tid]), ((const uint4*)g_wih) + cc * 256 + tid);
    };

    stage(0, 0);
    CP_COMMIT();

    for (int cc = 0; cc < 8; cc++) {
        if (cc < 7) {
            stage((cc + 1) & 1, cc + 1);
            CP_COMMIT();
            CP_WAIT1();
        } else {
            CP_WAIT0();
        }
        __syncthreads();

        uint4 a0 = sW1[cc & 1][(warpM * 2 + 0) * 32 + lane];
        uint4 a1 = sW1[cc & 1][(warpM * 2 + 1) * 32 + lane];
        const __half* ib = sB[cc & 1];
        uint2 bv[8];
#pragma unroll
        for (int j = 0; j < 8; j++) {
            int row = warpN * 4 + (j >> 1);
            int slot = (j & 1) * 8 + lq;
            bv[j] = *(const uint2*)(ib + (row * 16 + slot) * 16 + lr * 4);
        }
#pragma unroll
        for (int j = 0; j < 8; j++) {
            mma_f16(acc[0][j], a0, bv[j].x, bv[j].y);
            mma_f16(acc[1][j], a1, bv[j].x, bv[j].y);
        }
        __syncthreads();
    }

#pragma unroll
    for (int m = 0; m < 2; m++) {
        int oc = warpM * 32 + m * 16 + lq;
        float b0 = bi[oc], b1 = bi[oc + 8];
        __half* hf0 = g_feath + ((size_t)(b * CHN + oc)) * NPIX;
        __half* hf1 = hf0 + (size_t)8 * NPIX;
#pragma unroll
        for (int j = 0; j < 8; j++) {
            int pix = (r0 + warpN * 4 + (j >> 1)) * 128 + c0 + (j & 1) * 8 + lr * 2;
            *(__half2*)(hf0 + pix) = __floats2half2_rn(acc[m][j][0] + b0, acc[m][j][1] + b0);
            *(__half2*)(hf1 + pix) = __floats2half2_rn(acc[m][j][2] + b1, acc[m][j][3] + b1);
        }
    }
}

// ---------------- fused conv1 + 1x1 (role by blockIdx.z) ----------------------
__global__ __launch_bounds__(256, 2) void convA_kernel(const float* __restrict__ b1,
                                                       const float* __restrict__ bi)
{
    __shared__ __align__(16) char smemRaw[16384];
    const int z = blockIdx.z;
    const int r0 = blockIdx.y * 8;
    const int c0 = blockIdx.x * 16;
    if (z < 4) conv_role<true>(smemRaw, z, r0, c0, b1);
    else onebyone_role(smemRaw, z - 4, r0, c0, bi);
}

// ---------------- conv2 (standalone) ------------------------------------------
__global__ __launch_bounds__(256, 2) void conv2_kernel(const float* __restrict__ b2)
{
    __shared__ __align__(16) char smemRaw[11520];
    conv_role<false>(smemRaw, blockIdx.z, blockIdx.y * 8, blockIdx.x * 16, b2);
}

// ---------------- fused G = V V^T and t = V x1^T (role by blockIdx.x) ---------
// (Projection invariant to V row scaling; reference L1 normalization skipped.)
__global__ __launch_bounds__(256, 2) void gemmGT_kernel()
{
    __shared__ __half sV[2][128 * 24];   // stride 24 halves = 12 words, conflict-free
    __shared__ __half sX[2][64 * 24];
    const int tid = threadIdx.x;
    const int lane = tid & 31;
    const int wid = tid >> 5;
    const int warpM = wid & 3;
    const int warpN = wid >> 2;
    const int lq = lane >> 2;
    const int lr = lane & 3;
    const bool roleT = blockIdx.x >= NSLICE;
    const int slice = roleT ? (blockIdx.x - NSLICE) : blockIdx.x;
    const int b = blockIdx.y;
    const __half* vbase = g_feath + (size_t)b * CHN * NPIX;
    const __half* xbase = g_x1h + (size_t)b * 64 * NPIX;
    const int k0g = slice * 256;

    if (!roleT) {
        float acc[2][8][4];
#pragma unroll
        for (int mi = 0; mi < 2; mi++)
#pragma unroll
            for (int nj = 0; nj < 8; nj++)
#pragma unroll
                for (int e = 0; e < 4; e++) acc[mi][nj][e] = 0.f;

        auto stage = [&](int buf, int kc) {
            int kk = k0g + kc * 16;
            int c = tid >> 1, part = tid & 1;
            cp16(smem_u32(&sV[buf][c * 24 + part * 8]), vbase + (size_t)c * NPIX + kk + part * 8);
        };
        stage(0, 0);
        CP_COMMIT();

        for (int kc = 0; kc < 16; kc++) {
            if (kc < 15) {
                stage((kc + 1) & 1, kc + 1);
                CP_COMMIT();
                CP_WAIT1();
            } else {
                CP_WAIT0();
            }
            __syncthreads();
            const uint32_t* sv = (const uint32_t*)sV[kc & 1];   // row stride 12 words
            uint4 af[2];
#pragma unroll
            for (int mi = 0; mi < 2; mi++) {
                int m0 = warpM * 32 + mi * 16;
                af[mi].x = sv[(m0 + lq) * 12 + lr];
                af[mi].y = sv[(m0 + lq + 8) * 12 + lr];
                af[mi].z = sv[(m0 + lq) * 12 + 4 + lr];
                af[mi].w = sv[(m0 + lq + 8) * 12 + 4 + lr];
            }
#pragma unroll
            for (int nj = 0; nj < 8; nj++) {
                int n0 = warpN * 64 + nj * 8;
                uint32_t b0 = sv[(n0 + lq) * 12 + lr];
                uint32_t b1 = sv[(n0 + lq) * 12 + 4 + lr];
                mma_f16(acc[0][nj], af[0], b0, b1);
                mma_f16(acc[1][nj], af[1], b0, b1);
            }
            __syncthreads();
        }

        float* outp = g_gpart + ((size_t)slice * BATCH + b) * CHN * CHN;
#pragma unroll
        for (int mi = 0; mi < 2; mi++) {
            int m0 = warpM * 32 + mi * 16 + lq;
#pragma unroll
            for (int nj = 0; nj < 8; nj++) {
                int n = warpN * 64 + nj * 8 + lr * 2;
                *(float2*)(outp + m0 * 128 + n) = make_float2(acc[mi][nj][0], acc[mi][nj][1]);
                *(float2*)(outp + (m0 + 8) * 128 + n) = make_float2(acc[mi][nj][2], acc[mi][nj][3]);
            }
        }
    } else {
        float acc[2][4][4];
#pragma unroll
        for (int mi = 0; mi < 2; mi++)
#pragma unroll
            for (int nj = 0; nj < 4; nj++)
#pragma unroll
                for (int e = 0; e < 4; e++) acc[mi][nj][e] = 0.f;

        auto stage = [&](int buf, int kc) {
            int kk = k0g + kc * 16;
            int c = tid >> 1, part = tid & 1;
            cp16(smem_u32(&sV[buf][c * 24 + part * 8]), vbase + (size_t)c * NPIX + kk + part * 8);
            if (tid < 128)
                cp16(smem_u32(&sX[buf][c * 24 + part * 8]),
                     xbase + (size_t)c * NPIX + kk + part * 8);
        };
        stage(0, 0);
        CP_COMMIT();

        for (int kc = 0; kc < 16; kc++) {
            if (kc < 15) {
                stage((kc + 1) & 1, kc + 1);
                CP_COMMIT();
                CP_WAIT1();
            } else {
                CP_WAIT0();
            }
            __syncthreads();
            const uint32_t* sv = (const uint32_t*)sV[kc & 1];
            const uint32_t* sx = (const uint32_t*)sX[kc & 1];
            uint4 af[2];
#pragma unroll
            for (int mi = 0; mi < 2; mi++) {
                int m0 = warpM * 32 + mi * 16;
                af[mi].x = sv[(m0 + lq) * 12 + lr];
                af[mi].y = sv[(m0 + lq + 8) * 12 + lr];
                af[mi].z = sv[(m0 + lq) * 12 + 4 + lr];
                af[mi].w = sv[(m0 + lq + 8) * 12 + 4 + lr];
            }
#pragma unroll
            for (int nj = 0; nj < 4; nj++) {
                int n0 = warpN * 32 + nj * 8;
                uint32_t b0 = sx[(n0 + lq) * 12 + lr];
                uint32_t b1 = sx[(n0 + lq) * 12 + 4 + lr];
                mma_f16(acc[0][nj], af[0], b0, b1);
                mma_f16(acc[1][nj], af[1], b0, b1);
            }
            __syncthreads();
        }

        float* outp = g_tpart + ((size_t)slice * BATCH + b) * CHN * 64;
#pragma unroll
        for (int mi = 0; mi < 2; mi++) {
            int m0 = warpM * 32 + mi * 16 + lq;
#pragma unroll
            for (int nj = 0; nj < 4; nj++) {
                int n = warpN * 32 + nj * 8 + lr * 2;
                *(float2*)(outp + m0 * 64 + n) = make_float2(acc[mi][nj][0], acc[mi][nj][1]);
                *(float2*)(outp + (m0 + 8) * 64 + n) = make_float2(acc[mi][nj][2], acc[mi][nj][3]);
            }
        }
    }
}

// ---------------- reduce split-K partials for G and t (vectorized) ------------
__global__ void reduceGT_kernel()
{
    int o4 = blockIdx.x * 256 + threadIdx.x;
    const int NG4 = BATCH * CHN * CHN / 4;
    if (o4 < NG4) {
        float4 s = make_float4(0.f, 0.f, 0.f, 0.f);
        for (int sl = 0; sl < NSLICE; sl++) {
            float4 v = ((const float4*)g_gpart)[(size_t)sl * NG4 + o4];
            s.x += v.x; s.y += v.y; s.z += v.z; s.w += v.w;
        }
        ((float4*)g_G)[o4] = s;
    } else {
        int e4 = o4 - NG4;
        const int NT4 = BATCH * CHN * 64 / 4;
        if (e4 >= NT4) return;
        float4 s = make_float4(0.f, 0.f, 0.f, 0.f);
        for (int sl = 0; sl < NSLICE; sl++) {
            float4 v = ((const float4*)g_tpart)[(size_t)sl * NT4 + e4];
            s.x += v.x; s.y += v.y; s.z += v.z; s.w += v.w;
        }
        ((float4*)g_t)[e4] = s;
    }
}

// ---------------- solve: [G | t] -> G^{-1} t, register-resident GJ -----------
__global__ __launch_bounds__(768) void solve_kernel()
{
    __shared__ float fcol[128];
    __shared__ float prow[192];
    __shared__ float pinv_s;
    const int b = blockIdx.x, tid = threadIdx.x;
    const int j = tid % 192, g = tid / 192;

    float mv[32];
    if (j < 128) {
#pragma unroll
        for (int i = 0; i < 32; i++)
            mv[i] = g_G[(size_t)b * CHN * CHN + (size_t)(g * 32 + i) * 128 + j];
    } else {
        int m = j - 128;
#pragma unroll
        for (int i = 0; i < 32; i++)
            mv[i] = g_t[((size_t)b * CHN + g * 32 + i) * 64 + m];
    }

    for (int p = 0; p < 128; p++) {
        const int gp = p >> 5, pi = p & 31;
        if (j == p) {
#pragma unroll
            for (int i = 0; i < 32; i++) fcol[g * 32 + i] = mv[i];
            if (g == gp) pinv_s = 1.0f / mv[pi];
        }
        __syncthreads();
        if (g == gp) prow[j] = mv[pi] * pinv_s;
        __syncthreads();
        if (j >= 128 || j > p) {
            float pr = prow[j];
#pragma unroll
            for (int i = 0; i < 32; i++) {
                int row = g * 32 + i;
                float v = mv[i] - fcol[row] * pr;
                mv[i] = (row == p) ? pr : v;
            }
        }
        __syncthreads();
    }

    if (j >= 128) {
        int m = j - 128;
#pragma unroll
        for (int i = 0; i < 32; i++)
            g_t2[((size_t)b * CHN + g * 32 + i) * 64 + m] = mv[i];
    }
}

// ---------------- proj via fp16 mma: out[m][n] = sum_c t2[c][m] V[c][n] ------
// A = t2^T fp16 in smem [64][136]; B staged planar from g_feath [16c][264n].
__global__ __launch_bounds__(256, 2) void projh_kernel(float* __restrict__ out)
{
    __shared__ __half st2h[64 * 136];
    __shared__ __half sVt[2][16 * 264];

    const int tid = threadIdx.x;
    const int lane = tid & 31;
    const int wid = tid >> 5;
    const int lq = lane >> 2;
    const int lr = lane & 3;
    const int b = blockIdx.y;
    const int n0cta = blockIdx.x * 256;
    const __half* Vb = g_feath + (size_t)b * CHN * NPIX;

    // t2 transpose fp16 into smem: st2h[m][c]
    for (int e = tid; e < 8192; e += 256) {
        int c = e >> 6, m = e & 63;
        st2h[m * 136 + c] = __float2half_rn(g_t2[(size_t)b * CHN * 64 + e]);
    }

    auto stageV = [&](int buf, int cc) {
        int row = tid >> 4, part = tid & 15;
        const __half* src = Vb + (size_t)(cc * 16 + row) * NPIX + n0cta;
        cp16(smem_u32(&sVt[buf][row * 264 + part * 8]), src + part * 8);
        cp16(smem_u32(&sVt[buf][row * 264 + 128 + part * 8]), src + 128 + part * 8);
    };
    stageV(0, 0);
    CP_COMMIT();

    float acc[4][4][4];
#pragma unroll
    for (int mi = 0; mi < 4; mi++)
#pragma unroll
        for (int nj = 0; nj < 4; nj++)
#pragma unroll
            for (int e = 0; e < 4; e++) acc[mi][nj][e] = 0.f;

    for (int cc = 0; cc < 8; cc++) {
        if (cc < 7) {
            stageV((cc + 1) & 1, cc + 1);
            CP_COMMIT();
            CP_WAIT1();
        } else {
            CP_WAIT0();
        }
        __syncthreads();
        const uint32_t* s2 = (const uint32_t*)st2h;  // row stride 68 words
        const __half* sv = sVt[cc & 1];
        uint4 af[4];
#pragma unroll
        for (int mi = 0; mi < 4; mi++) {
            int m0 = mi * 16;
            af[mi].x = s2[(m0 + lq) * 68 + cc * 8 + lr];
            af[mi].y = s2[(m0 + lq + 8) * 68 + cc * 8 + lr];
            af[mi].z = s2[(m0 + lq) * 68 + cc * 8 + 4 + lr];
            af[mi].w = s2[(m0 + lq + 8) * 68 + cc * 8 + 4 + lr];
        }
#pragma unroll
        for (int nj = 0; nj < 4; nj++) {
            int n = wid * 32 + nj * 8 + lq;
            uint32_t b0 = pack_hh(sv[(2 * lr) * 264 + n], sv[(2 * lr + 1) * 264 + n]);
            uint32_t b1 = pack_hh(sv[(2 * lr + 8) * 264 + n], sv[(2 * lr + 9) * 264 + n]);
#pragma unroll
            for (int mi = 0; mi < 4; mi++) mma_f16(acc[mi][nj], af[mi], b0, b1);
        }
        __syncthreads();
    }

#pragma unroll
    for (int mi = 0; mi < 4; mi++) {
        int m0 = mi * 16 + lq;
#pragma unroll
        for (int nj = 0; nj < 4; nj++) {
            int n = n0cta + wid * 32 + nj * 8 + lr * 2;
            *(float2*)(out + ((size_t)(b * 64 + m0)) * NPIX + n) =
                make_float2(acc[mi][nj][0], acc[mi][nj][1]);
            *(float2*)(out + ((size_t)(b * 64 + m0 + 8)) * NPIX + n) =
                make_float2(acc[mi][nj][2], acc[mi][nj][3]);
        }
    }
}

// ---------------- launch -----------------------------------------------------
extern "C" void kernel_launch(void* const* d_in, const int* in_sizes, int n_in,
                              void* d_out, int out_size)
{
    const float* x1 = (const float*)d_in[0];
    const float* x2 = (const float*)d_in[1];
    const float* w1 = (const float*)d_in[2];
    const float* b1 = (const float*)d_in[3];
    const float* w2 = (const float*)d_in[4];
    const float* b2 = (const float*)d_in[5];
    const float* wi = (const float*)d_in[6];
    const float* bi = (const float*)d_in[7];
    float* out = (float*)d_out;

    uint32_t* wh1;  cudaGetSymbolAddress((void**)&wh1, g_wh1);
    uint32_t* wh2;  cudaGetSymbolAddress((void**)&wh2, g_wh2);
    uint32_t* wih;  cudaGetSymbolAddress((void**)&wih, g_wih);

    prep_repack_kernel<<<2200, 256>>>(x1, x2, w1, w2, wi, wh1, wh2, wih);

    convA_kernel<<<dim3(8, 16, 8), 256>>>(b1, bi);
    conv2_kernel<<<dim3(8, 16, 4), 256>>>(b2);

    gemmGT_kernel<<<dim3(2 * NSLICE, BATCH), 256>>>();
    reduceGT_kernel<<<96, 256>>>();
    solve_kernel<<<BATCH, 768>>>();
    projh_kernel<<<dim3(64, BATCH), 256>>>(out);
}